// round 16
// baseline (speedup 1.0000x reference)
#include <cuda_runtime.h>

static constexpr int Bb = 8;
static constexpr int Nn = 4096;
static constexpr int BLOCK = 1024;        // 32 warps
static constexpr int QPB = 256;           // queries per block
static constexpr int NSPLIT = 4;          // j-range split
static constexpr int SUBN = Nn / NSPLIT;  // 1024 candidates per thread

// smem: mx[4096] my[4096] mz[4096] s[4096] | sv[8*256] | sj[8*256]
// (mx,my,mz hold -2*coord; s holds |p|^2 of the ORIGINAL coords)
static constexpr int PTS_FLOATS = 4 * Nn;
static constexpr int SCR_FLOATS = 2 * NSPLIT * QPB;  // 2048
static constexpr int SMEM_BYTES = (PTS_FLOATS + 2 * SCR_FLOATS) * (int)sizeof(float);

#define HUGE_D2 3.0e38f

typedef unsigned long long u64;

__device__ __forceinline__ u64 pack2(float lo, float hi) {
    u64 r; asm("mov.b64 %0,{%1,%2};" : "=l"(r) : "f"(lo), "f"(hi)); return r;
}
__device__ __forceinline__ void unpack2(u64 v, float& lo, float& hi) {
    asm("mov.b64 {%0,%1},%2;" : "=f"(lo), "=f"(hi) : "l"(v));
}
__device__ __forceinline__ u64 fma2(u64 a, u64 b, u64 c) {
    u64 r; asm("fma.rn.f32x2 %0,%1,%2,%3;" : "=l"(r) : "l"(a), "l"(b), "l"(c)); return r;
}

// Rank key for fixed query i: d' = sj + xi*(-2xj) + yi*(-2yj) + zi*(-2zj)
//                                = d2_ij - si  (ordering identical; self ~= -si, strict min).
__device__ __forceinline__ u64 rank3f2(u64 mx, u64 my, u64 mz, u64 ps,
                                       u64 xi2, u64 yi2, u64 zi2) {
    return fma2(xi2, mx, fma2(yi2, my, fma2(zi2, mz, ps)));
}

// Stable top-3 insertion (strict <): earlier arrival wins ties, matching top_k.
#define UPD3(d, j)                                                   \
    do {                                                             \
        bool c1 = (d) < m1, c2 = (d) < m2, c3 = (d) < m3;            \
        float nm3 = c2 ? m2 : (c3 ? (d) : m3);                       \
        int   ni3 = c2 ? i2 : (c3 ? (j) : i3);                       \
        float nm2 = c1 ? m1 : (c2 ? (d) : m2);                       \
        int   ni2 = c1 ? i1 : (c2 ? (j) : i2);                       \
        m1 = c1 ? (d) : m1;  i1 = c1 ? (j) : i1;                     \
        m2 = nm2; i2 = ni2; m3 = nm3; i3 = ni3;                      \
    } while (0)

// Stable top-2 insertion.
#define UPD2(d, j)                                                   \
    do {                                                             \
        bool c1 = (d) < m1, c2 = (d) < m2;                           \
        float nm2 = c1 ? m1 : (c2 ? (d) : m2);                       \
        int   ni2 = c1 ? i1 : (c2 ? (j) : i2);                       \
        m1 = c1 ? (d) : m1;  i1 = c1 ? (j) : i1;                     \
        m2 = nm2; i2 = ni2;                                          \
    } while (0)

#define LOAD8(q, X0, X1, Y0, Y1, Z0, Z1, S0, S1)                     \
    do {                                                             \
        X0 = xs2[(q)]; X1 = xs2[(q) + 1];                            \
        Y0 = ys2[(q)]; Y1 = ys2[(q) + 1];                            \
        Z0 = zs2[(q)]; Z1 = zs2[(q) + 1];                            \
        S0 = ss2[(q)]; S1 = ss2[(q) + 1];                            \
    } while (0)

// Scan SUBN candidates starting at j0; return the two best non-self entries.
// HAS_SELF: the self point lies in this range and strictly owns the running min.
template <bool HAS_SELF>
__device__ __forceinline__ void scan_range(
    const float* __restrict__ sx, int j0,
    u64 xi2, u64 yi2, u64 zi2,
    float& o1, int& oi1, float& o2, int& oi2)
{
    const double2* xs2 = reinterpret_cast<const double2*>(sx);
    const double2* ys2 = reinterpret_cast<const double2*>(sx + Nn);
    const double2* zs2 = reinterpret_cast<const double2*>(sx + 2 * Nn);
    const double2* ss2 = reinterpret_cast<const double2*>(sx + 3 * Nn);

    float m1 = HUGE_D2, m2 = HUGE_D2, m3 = HUGE_D2;
    int   i1 = 0,       i2 = 0,       i3 = 0;

    // Software pipeline: prime batch j0.
    double2 X0, X1, Y0, Y1, Z0, Z1, S0, S1;
    LOAD8(j0 >> 2, X0, X1, Y0, Y1, Z0, Z1, S0, S1);

    for (int jb = j0; jb < j0 + SUBN; jb += 8) {
        // Distances for the CURRENT batch (3 packed fma per 2 candidates).
        const u64 dA = rank3f2(__double_as_longlong(X0.x), __double_as_longlong(Y0.x),
                               __double_as_longlong(Z0.x), __double_as_longlong(S0.x),
                               xi2, yi2, zi2);
        const u64 dB = rank3f2(__double_as_longlong(X0.y), __double_as_longlong(Y0.y),
                               __double_as_longlong(Z0.y), __double_as_longlong(S0.y),
                               xi2, yi2, zi2);
        const u64 dC = rank3f2(__double_as_longlong(X1.x), __double_as_longlong(Y1.x),
                               __double_as_longlong(Z1.x), __double_as_longlong(S1.x),
                               xi2, yi2, zi2);
        const u64 dD = rank3f2(__double_as_longlong(X1.y), __double_as_longlong(Y1.y),
                               __double_as_longlong(Z1.y), __double_as_longlong(S1.y),
                               xi2, yi2, zi2);

        // Prefetch NEXT batch before the divergent region (wrap to j0 on last iter;
        // the loaded values are discarded).
        {
            int jn = jb + 8;
            jn = (jn < j0 + SUBN) ? jn : j0;
            const int qn = jn >> 2;
            LOAD8(qn, X0, X1, Y0, Y1, Z0, Z1, S0, S1);
        }

        float d0, d1, e0, e1, f0, f1, g0, g1;
        unpack2(dA, d0, d1);
        unpack2(dB, e0, e1);
        unpack2(dC, f0, f1);
        unpack2(dD, g0, g1);

        const float pA = fminf(d0, d1);
        const float pB = fminf(e0, e1);
        const float pC = fminf(f0, f1);
        const float pD = fminf(g0, g1);
        const float mn = fminf(fminf(pA, pB), fminf(pC, pD));
        const float thr = HAS_SELF ? m3 : m2;

        if (mn < thr) {
            if (HAS_SELF) {
                if (pA < m3) { UPD3(d0, jb + 0); UPD3(d1, jb + 1); }
                if (pB < m3) { UPD3(e0, jb + 2); UPD3(e1, jb + 3); }
                if (pC < m3) { UPD3(f0, jb + 4); UPD3(f1, jb + 5); }
                if (pD < m3) { UPD3(g0, jb + 6); UPD3(g1, jb + 7); }
            } else {
                if (pA < m2) { UPD2(d0, jb + 0); UPD2(d1, jb + 1); }
                if (pB < m2) { UPD2(e0, jb + 2); UPD2(e1, jb + 3); }
                if (pC < m2) { UPD2(f0, jb + 4); UPD2(f1, jb + 5); }
                if (pD < m2) { UPD2(g0, jb + 6); UPD2(g1, jb + 7); }
            }
        }
    }

    if (HAS_SELF) {
        // slot 1 is self (strict minimum ~ -si); publish slots 2-3.
        o1 = m2; oi1 = i2; o2 = m3; oi2 = i3;
    } else {
        o1 = m1; oi1 = i1; o2 = m2; oi2 = i2;
    }
}

__global__ __launch_bounds__(BLOCK) void knn2_kernel(
    const float* __restrict__ coords,  // (B, N, 3) fp32
    float* __restrict__ out)           // A(B,N,3) | C(B,N,3) | idx1(B,N) | idx2(B,N)
{
    extern __shared__ float smem[];
    float* sx = smem;                                   // -2x
    float* sy = smem + Nn;                              // -2y
    float* sz = smem + 2 * Nn;                          // -2z
    float* ss = smem + 3 * Nn;                          // |p|^2
    float* sv = smem + PTS_FLOATS;                      // [8][QPB]
    int*   sj = (int*)(smem + PTS_FLOATS + SCR_FLOATS); // [8][QPB]

    const int bpb  = Nn / QPB;  // 16 blocks per batch
    const int b    = blockIdx.x / bpb;
    const int iblk = blockIdx.x % bpb;
    const float* cb = coords + (size_t)b * Nn * 3;

    for (int j = threadIdx.x; j < Nn; j += BLOCK) {
        float x = cb[3 * j + 0];
        float y = cb[3 * j + 1];
        float z = cb[3 * j + 2];
        float s = fmaf(z, z, fmaf(y, y, x * x));
        sx[j] = -2.0f * x; sy[j] = -2.0f * y; sz[j] = -2.0f * z; ss[j] = s;
    }
    __syncthreads();

    const int qid  = threadIdx.x & (QPB - 1);
    const int half = threadIdx.x >> 8;           // 0..3 (uniform per warp)
    const int i    = iblk * QPB + qid;           // batch-local query index
    // Recover original query coords exactly: x = -0.5 * (-2x).
    const float xi = -0.5f * sx[i];
    const float yi = -0.5f * sy[i];
    const float zi = -0.5f * sz[i];

    const u64 xi2 = pack2(xi, xi);
    const u64 yi2 = pack2(yi, yi);
    const u64 zi2 = pack2(zi, zi);

    // The split containing this block's queries (uniform per block).
    const int self_half = iblk >> 2;  // iblk*256 / 1024

    float o1, o2; int oi1, oi2;
    if (half == self_half) {
        scan_range<true >(sx, half * SUBN, xi2, yi2, zi2, o1, oi1, o2, oi2);
    } else {
        scan_range<false>(sx, half * SUBN, xi2, yi2, zi2, o1, oi1, o2, oi2);
    }

    // Publish per-half top-2 (self excluded). Layout [half*2+slot][qid]: conflict-free.
    sv[(half * 2 + 0) * QPB + qid] = o1;  sj[(half * 2 + 0) * QPB + qid] = oi1;
    sv[(half * 2 + 1) * QPB + qid] = o2;  sj[(half * 2 + 1) * QPB + qid] = oi2;
    __syncthreads();

    if (half == 0) {
        // Stable merge of 4 sorted pairs (ascending half = ascending index range).
        float m1 = HUGE_D2, m2 = HUGE_D2;
        int   i1 = 0,       i2 = 0;
#pragma unroll
        for (int k = 0; k < 2 * NSPLIT; ++k) {
            const float d = sv[k * QPB + qid];
            const int   j = sj[k * QPB + qid];
            UPD2(d, j);
        }

        const int j1 = i1;
        const int j2 = i2;

        const int BN3 = Bb * Nn * 3;
        const int BN  = Bb * Nn;
        const int gi  = b * Nn + i;
        const int base3 = gi * 3;

        // Coords recovered exactly from the -2-scaled tile.
        out[base3 + 0] = -0.5f * sx[j1];
        out[base3 + 1] = -0.5f * sy[j1];
        out[base3 + 2] = -0.5f * sz[j1];

        out[BN3 + base3 + 0] = -0.5f * sx[j2];
        out[BN3 + base3 + 1] = -0.5f * sy[j2];
        out[BN3 + base3 + 2] = -0.5f * sz[j2];

        out[2 * BN3 + gi]      = (float)j1;
        out[2 * BN3 + BN + gi] = (float)j2;
    }
    (void)ss;
}

extern "C" void kernel_launch(void* const* d_in, const int* in_sizes, int n_in,
                              void* d_out, int out_size) {
    (void)in_sizes; (void)n_in; (void)out_size;
    const float* coords = (const float*)d_in[0];
    float* out = (float*)d_out;

    cudaFuncSetAttribute(knn2_kernel,
                         cudaFuncAttributeMaxDynamicSharedMemorySize, SMEM_BYTES);

    dim3 grid(Bb * (Nn / QPB));  // 128 blocks
    dim3 block(BLOCK);
    knn2_kernel<<<grid, block, SMEM_BYTES>>>(coords, out);
}

// round 17
// speedup vs baseline: 1.2946x; 1.2946x over previous
#include <cuda_runtime.h>

static constexpr int Bb = 8;
static constexpr int Nn = 4096;
static constexpr int BLOCK = 1024;        // 32 warps
static constexpr int QPB = 256;           // queries per block
static constexpr int NSPLIT = 4;          // j-range split
static constexpr int SUBN = Nn / NSPLIT;  // 1024 candidates per thread

// smem: mx[4096] my[4096] mz[4096] s[4096] | sv[8*256] | sj[8*256]
static constexpr int PTS_FLOATS = 4 * Nn;
static constexpr int SCR_FLOATS = 2 * NSPLIT * QPB;  // 2048
static constexpr int SMEM_BYTES = (PTS_FLOATS + 2 * SCR_FLOATS) * (int)sizeof(float);

#define HUGE_D2 3.0e38f

typedef unsigned long long u64;

__device__ __forceinline__ u64 pack2(float lo, float hi) {
    u64 r; asm("mov.b64 %0,{%1,%2};" : "=l"(r) : "f"(lo), "f"(hi)); return r;
}
__device__ __forceinline__ void unpack2(u64 v, float& lo, float& hi) {
    asm("mov.b64 {%0,%1},%2;" : "=f"(lo), "=f"(hi) : "l"(v));
}
__device__ __forceinline__ u64 fma2(u64 a, u64 b, u64 c) {
    u64 r; asm("fma.rn.f32x2 %0,%1,%2,%3;" : "=l"(r) : "l"(a), "l"(b), "l"(c)); return r;
}

// Rank key: d' = sj + xi*(-2xj) + yi*(-2yj) + zi*(-2zj) = d2_ij - si.
// Deterministic fma sequence: recomputing on the same inputs is bitwise identical.
__device__ __forceinline__ u64 rank3f2(u64 mx, u64 my, u64 mz, u64 ps,
                                       u64 xi2, u64 yi2, u64 zi2) {
    return fma2(xi2, mx, fma2(yi2, my, fma2(zi2, mz, ps)));
}

// Stable top-2 insertion (strict <): earlier arrival wins ties.
#define UPD2(d, j)                                                   \
    do {                                                             \
        bool c1 = (d) < m1, c2 = (d) < m2;                           \
        float nm2 = c1 ? m1 : (c2 ? (d) : m2);                       \
        int   ni2 = c1 ? i1 : (c2 ? (j) : i2);                       \
        m1 = c1 ? (d) : m1;  i1 = c1 ? (j) : i1;                     \
        m2 = nm2; i2 = ni2;                                          \
    } while (0)

// Compute the 8 rank keys of batch jb into d[0..7]. Identical instruction
// sequence for scan and recovery passes (bitwise-reproducible).
__device__ __forceinline__ void batch_keys(
    const double2* __restrict__ xs2, const double2* __restrict__ ys2,
    const double2* __restrict__ zs2, const double2* __restrict__ ss2,
    int jb, u64 xi2, u64 yi2, u64 zi2, float* d)
{
    const int q = jb >> 2;
    const double2 X0 = xs2[q], X1 = xs2[q + 1];
    const double2 Y0 = ys2[q], Y1 = ys2[q + 1];
    const double2 Z0 = zs2[q], Z1 = zs2[q + 1];
    const double2 S0 = ss2[q], S1 = ss2[q + 1];

    const u64 dA = rank3f2(__double_as_longlong(X0.x), __double_as_longlong(Y0.x),
                           __double_as_longlong(Z0.x), __double_as_longlong(S0.x),
                           xi2, yi2, zi2);
    const u64 dB = rank3f2(__double_as_longlong(X0.y), __double_as_longlong(Y0.y),
                           __double_as_longlong(Z0.y), __double_as_longlong(S0.y),
                           xi2, yi2, zi2);
    const u64 dC = rank3f2(__double_as_longlong(X1.x), __double_as_longlong(Y1.x),
                           __double_as_longlong(Z1.x), __double_as_longlong(S1.x),
                           xi2, yi2, zi2);
    const u64 dD = rank3f2(__double_as_longlong(X1.y), __double_as_longlong(Y1.y),
                           __double_as_longlong(Z1.y), __double_as_longlong(S1.y),
                           xi2, yi2, zi2);
    unpack2(dA, d[0], d[1]);
    unpack2(dB, d[2], d[3]);
    unpack2(dC, d[4], d[5]);
    unpack2(dD, d[6], d[7]);
}

// Recover the (lowest) index k in batch jb whose key equals val, excluding
// index exclj. HAS_SELF: mask the self candidate exactly as the scan did.
template <bool HAS_SELF>
__device__ __forceinline__ int recover_index(
    const double2* xs2, const double2* ys2, const double2* zs2, const double2* ss2,
    int jb, u64 xi2, u64 yi2, u64 zi2, float val, int selfi, int exclj)
{
    float d[8];
    batch_keys(xs2, ys2, zs2, ss2, jb, xi2, yi2, zi2, d);
    int j = -1;
#pragma unroll
    for (int k = 7; k >= 0; --k) {
        bool m = (d[k] == val) && (jb + k != exclj);
        if (HAS_SELF) m = m && (jb + k != selfi);
        j = m ? (jb + k) : j;   // descending: lowest k wins
    }
    return j;
}

// Branchless scan of SUBN candidates from j0: running top-2 VALUES + source
// batch ids; indices recovered afterwards from the two batches.
template <bool HAS_SELF>
__device__ __forceinline__ void scan_range(
    const float* __restrict__ sx, int j0, int selfi,
    u64 xi2, u64 yi2, u64 zi2,
    float& o1, int& oi1, float& o2, int& oi2)
{
    const double2* xs2 = reinterpret_cast<const double2*>(sx);
    const double2* ys2 = reinterpret_cast<const double2*>(sx + Nn);
    const double2* zs2 = reinterpret_cast<const double2*>(sx + 2 * Nn);
    const double2* ss2 = reinterpret_cast<const double2*>(sx + 3 * Nn);

    float m1 = HUGE_D2, m2 = HUGE_D2;
    int   b1 = j0,      b2 = j0;
    const int selfbatch = selfi & ~7;

#pragma unroll 2
    for (int jb = j0; jb < j0 + SUBN; jb += 8) {
        float d[8];
        batch_keys(xs2, ys2, zs2, ss2, jb, xi2, yi2, zi2, d);

        if (HAS_SELF) {
            // Rare (4 batches per warp): mask the self candidate to HUGE.
            if (__any_sync(0xffffffffu, jb == selfbatch)) {
#pragma unroll
                for (int k = 0; k < 8; ++k)
                    d[k] = (jb + k == selfi) ? HUGE_D2 : d[k];
            }
        }

        // Branchless top-2-of-8 tournament.
        const float lo0 = fminf(d[0], d[1]), hi0 = fmaxf(d[0], d[1]);
        const float lo1 = fminf(d[2], d[3]), hi1 = fmaxf(d[2], d[3]);
        const float lo2 = fminf(d[4], d[5]), hi2 = fmaxf(d[4], d[5]);
        const float lo3 = fminf(d[6], d[7]), hi3 = fmaxf(d[6], d[7]);
        const float qm0 = fminf(lo0, lo1);
        const float qs0 = fminf(fmaxf(lo0, lo1), fminf(hi0, hi1));
        const float qm1 = fminf(lo2, lo3);
        const float qs1 = fminf(fmaxf(lo2, lo3), fminf(hi2, hi3));
        const float a = fminf(qm0, qm1);                              // batch min
        const float s = fminf(fmaxf(qm0, qm1), fminf(qs0, qs1));      // batch 2nd

        // Merge into running (m1,b1),(m2,b2) — branchless, batch-id tracking.
        const bool c1 = a < m1;
        const bool cs = s < m1;
        const bool c2 = a < m2;
        const float nm2 = fminf(fmaxf(m1, a), fminf(m2, s));
        b2 = c1 ? (cs ? jb : b1) : (c2 ? jb : b2);
        b1 = c1 ? jb : b1;
        m2 = nm2;
        m1 = fminf(m1, a);
    }

    // Index recovery: rescan only the two source batches (bitwise-equal keys).
    const int j1 = recover_index<HAS_SELF>(xs2, ys2, zs2, ss2, b1,
                                           xi2, yi2, zi2, m1, selfi, -1);
    const int excl = (m2 == m1 && b2 == b1) ? j1 : -1;  // within-batch tie
    const int j2 = recover_index<HAS_SELF>(xs2, ys2, zs2, ss2, b2,
                                           xi2, yi2, zi2, m2, selfi, excl);

    o1 = m1; oi1 = j1; o2 = m2; oi2 = j2;
}

__global__ __launch_bounds__(BLOCK) void knn2_kernel(
    const float* __restrict__ coords,  // (B, N, 3) fp32
    float* __restrict__ out)           // A(B,N,3) | C(B,N,3) | idx1(B,N) | idx2(B,N)
{
    extern __shared__ float smem[];
    float* sx = smem;                                   // -2x
    float* sy = smem + Nn;                              // -2y
    float* sz = smem + 2 * Nn;                          // -2z
    float* ss = smem + 3 * Nn;                          // |p|^2
    float* sv = smem + PTS_FLOATS;                      // [8][QPB]
    int*   sj = (int*)(smem + PTS_FLOATS + SCR_FLOATS); // [8][QPB]

    const int bpb  = Nn / QPB;  // 16 blocks per batch
    const int b    = blockIdx.x / bpb;
    const int iblk = blockIdx.x % bpb;
    const float* cb = coords + (size_t)b * Nn * 3;

    for (int j = threadIdx.x; j < Nn; j += BLOCK) {
        float x = cb[3 * j + 0];
        float y = cb[3 * j + 1];
        float z = cb[3 * j + 2];
        float s = fmaf(z, z, fmaf(y, y, x * x));
        sx[j] = -2.0f * x; sy[j] = -2.0f * y; sz[j] = -2.0f * z; ss[j] = s;
    }
    __syncthreads();

    const int qid  = threadIdx.x & (QPB - 1);
    const int half = threadIdx.x >> 8;           // 0..3 (uniform per warp)
    const int i    = iblk * QPB + qid;           // batch-local query index
    const float xi = -0.5f * sx[i];
    const float yi = -0.5f * sy[i];
    const float zi = -0.5f * sz[i];

    const u64 xi2 = pack2(xi, xi);
    const u64 yi2 = pack2(yi, yi);
    const u64 zi2 = pack2(zi, zi);

    const int self_half = iblk >> 2;  // split containing this block's queries

    float o1, o2; int oi1, oi2;
    if (half == self_half) {
        scan_range<true >(sx, half * SUBN, i, xi2, yi2, zi2, o1, oi1, o2, oi2);
    } else {
        scan_range<false>(sx, half * SUBN, i, xi2, yi2, zi2, o1, oi1, o2, oi2);
    }

    sv[(half * 2 + 0) * QPB + qid] = o1;  sj[(half * 2 + 0) * QPB + qid] = oi1;
    sv[(half * 2 + 1) * QPB + qid] = o2;  sj[(half * 2 + 1) * QPB + qid] = oi2;
    __syncthreads();

    if (half == 0) {
        // Stable merge of 4 sorted pairs (ascending half = ascending index range).
        float m1 = HUGE_D2, m2 = HUGE_D2;
        int   i1 = 0,       i2 = 0;
#pragma unroll
        for (int k = 0; k < 2 * NSPLIT; ++k) {
            const float d = sv[k * QPB + qid];
            const int   j = sj[k * QPB + qid];
            UPD2(d, j);
        }

        const int j1 = i1;
        const int j2 = i2;

        const int BN3 = Bb * Nn * 3;
        const int BN  = Bb * Nn;
        const int gi  = b * Nn + i;
        const int base3 = gi * 3;

        out[base3 + 0] = -0.5f * sx[j1];
        out[base3 + 1] = -0.5f * sy[j1];
        out[base3 + 2] = -0.5f * sz[j1];

        out[BN3 + base3 + 0] = -0.5f * sx[j2];
        out[BN3 + base3 + 1] = -0.5f * sy[j2];
        out[BN3 + base3 + 2] = -0.5f * sz[j2];

        out[2 * BN3 + gi]      = (float)j1;
        out[2 * BN3 + BN + gi] = (float)j2;
    }
    (void)ss;
}

extern "C" void kernel_launch(void* const* d_in, const int* in_sizes, int n_in,
                              void* d_out, int out_size) {
    (void)in_sizes; (void)n_in; (void)out_size;
    const float* coords = (const float*)d_in[0];
    float* out = (float*)d_out;

    cudaFuncSetAttribute(knn2_kernel,
                         cudaFuncAttributeMaxDynamicSharedMemorySize, SMEM_BYTES);

    dim3 grid(Bb * (Nn / QPB));  // 128 blocks
    dim3 block(BLOCK);
    knn2_kernel<<<grid, block, SMEM_BYTES>>>(coords, out);
}